// round 14
// baseline (speedup 1.0000x reference)
#include <cuda_runtime.h>
#include <cuda_bf16.h>
#include <cstdint>

#define N_NODES 50000
#define N_EDGES 600000
#define N_GRAPHS 64
#define SCAN_BLOCKS ((N_NODES + 1023) / 1024)   // 49
#define HIST_B 512

// ---------------- scratch (no allocations allowed) ----------------
__device__ float g_t[(size_t)N_NODES * 128];   // GEMM output t = h@W (raw)
__device__ float g_h[(size_t)N_NODES * 128];   // layer activations
__device__ float g_dinv[N_NODES];
__device__ int   g_indeg[N_NODES];
__device__ int   g_rowptr[N_NODES + 1];
__device__ int   g_cursor[N_NODES];
__device__ int   g_csrsrc[N_EDGES];
__device__ int   g_bsum[SCAN_BLOCKS];
__device__ float g_pool[N_GRAPHS * 64];
__device__ float g_cnt[N_GRAPHS];
__device__ int   g_is64;

// index loader robust to int32 vs int64 storage
__device__ __forceinline__ int load_idx(const void* __restrict__ p, size_t i) {
    if (g_is64) return (int)((const long long*)p)[i];
    return ((const int*)p)[i];
}

// ---------------- zero + dtype detect (fused) ----------------
__global__ void k_zero(const int* __restrict__ ei_words) {
    int i = blockIdx.x * blockDim.x + threadIdx.x;
    int stride = gridDim.x * blockDim.x;
    if (blockIdx.x == 0 && threadIdx.x < 32) {
        int lane = threadIdx.x;
        int nz = 0;
        for (int j = lane; j < 256; j += 32)
            nz |= ei_words[2 * j + 1];          // candidate int64 high words
        for (int off = 16; off; off >>= 1)
            nz |= __shfl_xor_sync(0xffffffffu, nz, off);
        if (lane == 0) g_is64 = (nz == 0) ? 1 : 0;
    }
    for (int j = i; j < N_NODES; j += stride) { g_indeg[j] = 0; g_cursor[j] = 0; }
    if (i < N_GRAPHS * 64) g_pool[i] = 0.f;
    if (i < N_GRAPHS) g_cnt[i] = 0.f;
}

__global__ void k_scan1() {
    int tid = threadIdx.x;
    int i = blockIdx.x * 1024 + tid;
    int lane = tid & 31, wid = tid >> 5;
    int v = (i < N_NODES) ? g_indeg[i] : 0;
    if (i < N_NODES) g_dinv[i] = rsqrtf((float)(v + 1));
    int s = v;
    #pragma unroll
    for (int off = 1; off < 32; off <<= 1) {
        int t = __shfl_up_sync(0xffffffffu, s, off);
        if (lane >= off) s += t;
    }
    __shared__ int wsum[32];
    if (lane == 31) wsum[wid] = s;
    __syncthreads();
    if (wid == 0) {
        int w = wsum[lane];
        #pragma unroll
        for (int off = 1; off < 32; off <<= 1) {
            int t = __shfl_up_sync(0xffffffffu, w, off);
            if (lane >= off) w += t;
        }
        wsum[lane] = w;
    }
    __syncthreads();
    int incl = s + (wid ? wsum[wid - 1] : 0);
    if (i < N_NODES) g_rowptr[i + 1] = incl;
    if (tid == 1023) g_bsum[blockIdx.x] = incl;
}

// scan3: each block computes its own carry from g_bsum (replaces k_scan2)
__global__ void k_scan3() {
    __shared__ int soff;
    int tid = threadIdx.x, lane = tid & 31;
    if (tid < 32) {
        int acc = 0;
        for (int j = lane; j < blockIdx.x; j += 32) acc += g_bsum[j];
        #pragma unroll
        for (int off = 16; off; off >>= 1)
            acc += __shfl_xor_sync(0xffffffffu, acc, off);
        if (lane == 0) soff = acc;
    }
    __syncthreads();
    int i = blockIdx.x * 1024 + tid;
    if (i < N_NODES) g_rowptr[i + 1] += soff;
    if (i == 0) g_rowptr[0] = 0;
}

__global__ void k_fill(const void* __restrict__ ei) {
    int e = blockIdx.x * blockDim.x + threadIdx.x;
    if (e < N_EDGES) {
        int c = load_idx(ei, (size_t)N_EDGES + e);
        int pos = g_rowptr[c] + atomicAdd(&g_cursor[c], 1);
        g_csrsrc[pos] = load_idx(ei, e);
    }
}

// ---------------- HMMA GEMM: g_t = A @ W (raw, no dinv) ----------------
// bf16 hi/lo split, 3-term mma.sync (Ah*Bh + Ah*Bl + Al*Bh), fp32 acc.
// B = W^T staged in smem. A fragments loaded directly from gmem per warp.
// WITH_HIST: blocks >= mb instead histogram edge destinations (overlap).
#define APAD 136

__device__ __forceinline__ void mma16816(float* d, const uint32_t* a,
                                         uint32_t b0, uint32_t b1) {
    asm volatile(
        "mma.sync.aligned.m16n8k16.row.col.f32.bf16.bf16.f32 "
        "{%0,%1,%2,%3}, {%4,%5,%6,%7}, {%8,%9}, {%0,%1,%2,%3};"
        : "+f"(d[0]), "+f"(d[1]), "+f"(d[2]), "+f"(d[3])
        : "r"(a[0]), "r"(a[1]), "r"(a[2]), "r"(a[3]), "r"(b0), "r"(b1));
}

__device__ __forceinline__ void split2(float2 v, uint32_t& hi, uint32_t& lo) {
    __nv_bfloat16 h0 = __float2bfloat16(v.x), h1 = __float2bfloat16(v.y);
    __nv_bfloat16 l0 = __float2bfloat16(v.x - __bfloat162float(h0));
    __nv_bfloat16 l1 = __float2bfloat16(v.y - __bfloat162float(h1));
    __nv_bfloat162 H(h0, h1), L(l0, l1);
    hi = *(uint32_t*)&H;
    lo = *(uint32_t*)&L;
}

template <int NC, bool FROM_GH, bool WITH_HIST>
__global__ __launch_bounds__(256, 2) void k_mma(const float* __restrict__ Ax,
                                                const float* __restrict__ W,
                                                const void* __restrict__ ei,
                                                int mb) {
    const int tid = threadIdx.x;

    if (WITH_HIST && (int)blockIdx.x >= mb) {
        // histogram part: grid-stride over edge destinations
        size_t t = (size_t)((int)blockIdx.x - mb) * 256 + tid;
        for (size_t e = t; e < N_EDGES; e += (size_t)HIST_B * 256)
            atomicAdd(&g_indeg[load_idx(ei, (size_t)N_EDGES + e)], 1);
        return;
    }

    const float* __restrict__ A = FROM_GH ? (const float*)g_h : Ax;
    extern __shared__ __nv_bfloat16 sm[];
    __nv_bfloat16* BH = sm;                    // [NC][APAD]
    __nv_bfloat16* BL = BH + NC * APAD;

    const int wid = tid >> 5, lane = tid & 31;
    const int base = blockIdx.x * 128;

    // ---- stage B = W^T: W[k][n] -> B[n][k], hi/lo split ----
    for (int idx = tid; idx < 128 * NC; idx += 256) {
        int k = idx / NC, n = idx % NC;        // coalesced W read
        float w = W[idx];
        __nv_bfloat16 h = __float2bfloat16(w);
        BH[n * APAD + k] = h;
        BL[n * APAD + k] = __float2bfloat16(w - __bfloat162float(h));
    }
    __syncthreads();

    constexpr int NT = NC / 8;
    float acc[NT][4];
    #pragma unroll
    for (int t = 0; t < NT; t++)
        #pragma unroll
        for (int j = 0; j < 4; j++) acc[t][j] = 0.f;

    const int g = lane >> 2;                   // 0..7
    const int kq = (lane & 3) * 2;             // 0,2,4,6
    const int r0 = wid * 16 + g, r1 = r0 + 8;
    const int gr0 = base + r0, gr1 = base + r1;
    const bool v0 = gr0 < N_NODES, v1 = gr1 < N_NODES;
    const float* A0 = A + (size_t)gr0 * 128;
    const float* A1 = A + (size_t)gr1 * 128;

    #pragma unroll
    for (int ks = 0; ks < 8; ks++) {
        int kb = ks * 16 + kq;
        float2 z = make_float2(0.f, 0.f);
        float2 va0 = v0 ? *(const float2*)(A0 + kb)     : z;
        float2 va1 = v1 ? *(const float2*)(A1 + kb)     : z;
        float2 vb0 = v0 ? *(const float2*)(A0 + kb + 8) : z;
        float2 vb1 = v1 ? *(const float2*)(A1 + kb + 8) : z;
        uint32_t ah[4], al[4];
        split2(va0, ah[0], al[0]);
        split2(va1, ah[1], al[1]);
        split2(vb0, ah[2], al[2]);
        split2(vb1, ah[3], al[3]);
        #pragma unroll
        for (int nt = 0; nt < NT; nt++) {
            int n = nt * 8 + g;
            uint32_t bh0 = *(const uint32_t*)(BH + n * APAD + kb);
            uint32_t bh1 = *(const uint32_t*)(BH + n * APAD + kb + 8);
            uint32_t bl0 = *(const uint32_t*)(BL + n * APAD + kb);
            uint32_t bl1 = *(const uint32_t*)(BL + n * APAD + kb + 8);
            mma16816(acc[nt], ah, bh0, bh1);
            mma16816(acc[nt], ah, bl0, bl1);
            mma16816(acc[nt], al, bh0, bh1);
        }
    }

    // ---- epilogue: write raw t ----
    #pragma unroll
    for (int nt = 0; nt < NT; nt++) {
        int col = nt * 8 + kq;
        if (v0)
            *(float2*)(g_t + (size_t)gr0 * NC + col) = make_float2(acc[nt][0], acc[nt][1]);
        if (v1)
            *(float2*)(g_t + (size_t)gr1 * NC + col) = make_float2(acc[nt][2], acc[nt][3]);
    }
}

// ---------------- aggregation (layers 1,2): g_h = relu(d_v*(sum d_s*t_s + d_v*t_v)+b) ----------------
__global__ void k_agg128(const float* __restrict__ bias) {
    int gw = (blockIdx.x * blockDim.x + threadIdx.x) >> 5;
    int lane = threadIdx.x & 31;
    if (gw >= N_NODES) return;
    int beg = g_rowptr[gw], end = g_rowptr[gw + 1];
    float d = g_dinv[gw];

    float4 t = *((const float4*)(g_t + (size_t)gw * 128) + lane);
    float4 a = make_float4(d * t.x, d * t.y, d * t.z, d * t.w);  // self term
    int e = beg;
    for (; e + 4 <= end; e += 4) {
        int s0 = g_csrsrc[e], s1 = g_csrsrc[e + 1], s2 = g_csrsrc[e + 2], s3 = g_csrsrc[e + 3];
        float d0 = g_dinv[s0], d1 = g_dinv[s1], d2 = g_dinv[s2], d3 = g_dinv[s3];
        float4 u0 = *((const float4*)(g_t + (size_t)s0 * 128) + lane);
        float4 u1 = *((const float4*)(g_t + (size_t)s1 * 128) + lane);
        float4 u2 = *((const float4*)(g_t + (size_t)s2 * 128) + lane);
        float4 u3 = *((const float4*)(g_t + (size_t)s3 * 128) + lane);
        a.x = fmaf(d0, u0.x, fmaf(d1, u1.x, fmaf(d2, u2.x, fmaf(d3, u3.x, a.x))));
        a.y = fmaf(d0, u0.y, fmaf(d1, u1.y, fmaf(d2, u2.y, fmaf(d3, u3.y, a.y))));
        a.z = fmaf(d0, u0.z, fmaf(d1, u1.z, fmaf(d2, u2.z, fmaf(d3, u3.z, a.z))));
        a.w = fmaf(d0, u0.w, fmaf(d1, u1.w, fmaf(d2, u2.w, fmaf(d3, u3.w, a.w))));
    }
    for (; e < end; e++) {
        int s = g_csrsrc[e];
        float ds = g_dinv[s];
        float4 u = *((const float4*)(g_t + (size_t)s * 128) + lane);
        a.x = fmaf(ds, u.x, a.x); a.y = fmaf(ds, u.y, a.y);
        a.z = fmaf(ds, u.z, a.z); a.w = fmaf(ds, u.w, a.w);
    }
    float4 bb = *((const float4*)bias + lane);
    float4 o;
    o.x = fmaxf(fmaf(d, a.x, bb.x), 0.f);
    o.y = fmaxf(fmaf(d, a.y, bb.y), 0.f);
    o.z = fmaxf(fmaf(d, a.z, bb.z), 0.f);
    o.w = fmaxf(fmaf(d, a.w, bb.w), 0.f);
    *((float4*)(g_h + (size_t)gw * 128) + lane) = o;
}

// ---------------- layer-3 aggregation fused with mean-pool accumulation ----------------
__global__ void k_agg_pool(const float* __restrict__ bias, const void* __restrict__ batch) {
    int gw = (blockIdx.x * blockDim.x + threadIdx.x) >> 5;
    int lane = threadIdx.x & 31;
    if (gw >= N_NODES) return;
    int beg = g_rowptr[gw], end = g_rowptr[gw + 1];
    float d = g_dinv[gw];

    float2 t = *((const float2*)(g_t + (size_t)gw * 64) + lane);
    float2 a = make_float2(d * t.x, d * t.y);
    int e = beg;
    for (; e + 4 <= end; e += 4) {
        int s0 = g_csrsrc[e], s1 = g_csrsrc[e + 1], s2 = g_csrsrc[e + 2], s3 = g_csrsrc[e + 3];
        float d0 = g_dinv[s0], d1 = g_dinv[s1], d2 = g_dinv[s2], d3 = g_dinv[s3];
        float2 u0 = *((const float2*)(g_t + (size_t)s0 * 64) + lane);
        float2 u1 = *((const float2*)(g_t + (size_t)s1 * 64) + lane);
        float2 u2 = *((const float2*)(g_t + (size_t)s2 * 64) + lane);
        float2 u3 = *((const float2*)(g_t + (size_t)s3 * 64) + lane);
        a.x = fmaf(d0, u0.x, fmaf(d1, u1.x, fmaf(d2, u2.x, fmaf(d3, u3.x, a.x))));
        a.y = fmaf(d0, u0.y, fmaf(d1, u1.y, fmaf(d2, u2.y, fmaf(d3, u3.y, a.y))));
    }
    for (; e < end; e++) {
        int s = g_csrsrc[e];
        float ds = g_dinv[s];
        float2 u = *((const float2*)(g_t + (size_t)s * 64) + lane);
        a.x = fmaf(ds, u.x, a.x); a.y = fmaf(ds, u.y, a.y);
    }
    float2 bb = *((const float2*)bias + lane);
    float ox = fmaxf(fmaf(d, a.x, bb.x), 0.f);
    float oy = fmaxf(fmaf(d, a.y, bb.y), 0.f);

    int g = load_idx(batch, gw);
    atomicAdd(&g_pool[g * 64 + lane * 2], ox);
    atomicAdd(&g_pool[g * 64 + lane * 2 + 1], oy);
    if (lane == 0) atomicAdd(&g_cnt[g], 1.f);
}

// ---------------- FC head (single block) ----------------
__global__ void k_fc(const float* __restrict__ Wf1, const float* __restrict__ bf1,
                     const float* __restrict__ Wf2, const float* __restrict__ bf2,
                     float* __restrict__ out) {
    __shared__ float p[64 * 64];
    __shared__ float a1[64 * 32];
    int tid = threadIdx.x;
    for (int i = tid; i < 64 * 64; i += 256) {
        int g = i >> 6;
        p[i] = g_pool[i] / fmaxf(g_cnt[g], 1.f);
    }
    __syncthreads();
    for (int i = tid; i < 64 * 32; i += 256) {
        int g = i >> 5, c = i & 31;
        float s = bf1[c];
        #pragma unroll 8
        for (int k = 0; k < 64; k++) s = fmaf(p[g * 64 + k], Wf1[k * 32 + c], s);
        a1[i] = fmaxf(s, 0.f);
    }
    __syncthreads();
    for (int i = tid; i < 64 * 10; i += 256) {
        int g = i / 10, c = i % 10;
        float s = bf2[c];
        #pragma unroll
        for (int k = 0; k < 32; k++) s = fmaf(a1[g * 32 + k], Wf2[k * 10 + c], s);
        out[i] = s;
    }
}

// ---------------- launch ----------------
extern "C" void kernel_launch(void* const* d_in, const int* in_sizes, int n_in,
                              void* d_out, int out_size) {
    const float* x     = (const float*)d_in[0];
    const void*  ei    = d_in[1];
    const void*  batch = d_in[2];
    const float* W1  = (const float*)d_in[3];
    const float* b1  = (const float*)d_in[4];
    const float* W2  = (const float*)d_in[5];
    const float* b2  = (const float*)d_in[6];
    const float* W3  = (const float*)d_in[7];
    const float* b3  = (const float*)d_in[8];
    const float* Wf1 = (const float*)d_in[9];
    const float* bf1 = (const float*)d_in[10];
    const float* Wf2 = (const float*)d_in[11];
    const float* bf2 = (const float*)d_in[12];
    float* out = (float*)d_out;

    const int EB = (N_EDGES + 255) / 256;
    const int AB = (N_NODES * 32 + 255) / 256;
    const int MB = (N_NODES + 127) / 128;      // 391

    const int SM128 = 2 * 128 * APAD * 2;      // 69632 (B hi+lo)
    const int SM64  = 2 * 64 * APAD * 2;       // 34816
    cudaFuncSetAttribute(k_mma<128, false, true>, cudaFuncAttributeMaxDynamicSharedMemorySize, SM128);
    cudaFuncSetAttribute(k_mma<128, true, false>, cudaFuncAttributeMaxDynamicSharedMemorySize, SM128);
    cudaFuncSetAttribute(k_mma<64, true, false>,  cudaFuncAttributeMaxDynamicSharedMemorySize, SM64);

    k_zero<<<64, 256>>>((const int*)ei);
    // GEMM-1 (independent of CSR) overlapped with edge histogram
    k_mma<128, false, true><<<MB + HIST_B, 256, SM128>>>(x, W1, ei, MB);
    k_scan1<<<SCAN_BLOCKS, 1024>>>();
    k_scan3<<<SCAN_BLOCKS, 1024>>>();
    k_fill<<<EB, 256>>>(ei);

    k_agg128<<<AB, 256>>>(b1);
    k_mma<128, true, false><<<MB, 256, SM128>>>(nullptr, W2, nullptr, MB);
    k_agg128<<<AB, 256>>>(b2);
    k_mma<64, true, false><<<MB, 256, SM64>>>(nullptr, W3, nullptr, MB);
    k_agg_pool<<<AB, 256>>>(b3, batch);

    k_fc<<<1, 256>>>(Wf1, bf1, Wf2, bf2, out);
}

// round 15
// speedup vs baseline: 1.3543x; 1.3543x over previous
#include <cuda_runtime.h>
#include <cuda_bf16.h>
#include <cstdint>

#define N_NODES 50000
#define N_EDGES 600000
#define N_GRAPHS 64
#define SCAN_BLOCKS ((N_NODES + 1023) / 1024)   // 49

// ---------------- scratch (no allocations allowed) ----------------
__device__ float g_t[(size_t)N_NODES * 128];   // GEMM output u = dinv * (h@W)
__device__ float g_h[(size_t)N_NODES * 128];   // layer activations
__device__ float g_dinv[N_NODES];
__device__ int   g_indeg[N_NODES];
__device__ int   g_rowptr[N_NODES + 1];
__device__ int   g_cursor[N_NODES];
__device__ int   g_csrsrc[N_EDGES];
__device__ int   g_bsum[SCAN_BLOCKS];
__device__ float g_pool[N_GRAPHS * 64];
__device__ float g_cnt[N_GRAPHS];
__device__ int   g_is64;

// index loader robust to int32 vs int64 storage
__device__ __forceinline__ int load_idx(const void* __restrict__ p, size_t i) {
    if (g_is64) return (int)((const long long*)p)[i];
    return ((const int*)p)[i];
}

// ---------------- zero + dtype detect (fused) ----------------
__global__ void k_zero(const int* __restrict__ ei_words) {
    int i = blockIdx.x * blockDim.x + threadIdx.x;
    int stride = gridDim.x * blockDim.x;
    if (blockIdx.x == 0 && threadIdx.x < 32) {
        int lane = threadIdx.x;
        int nz = 0;
        for (int j = lane; j < 256; j += 32)
            nz |= ei_words[2 * j + 1];          // candidate int64 high words
        for (int off = 16; off; off >>= 1)
            nz |= __shfl_xor_sync(0xffffffffu, nz, off);
        if (lane == 0) g_is64 = (nz == 0) ? 1 : 0;
    }
    for (int j = i; j < N_NODES; j += stride) { g_indeg[j] = 0; g_cursor[j] = 0; }
    if (i < N_GRAPHS * 64) g_pool[i] = 0.f;
    if (i < N_GRAPHS) g_cnt[i] = 0.f;
}

__global__ void k_hist(const void* __restrict__ ei) {
    int e = blockIdx.x * blockDim.x + threadIdx.x;
    if (e < N_EDGES) atomicAdd(&g_indeg[load_idx(ei, (size_t)N_EDGES + e)], 1);
}

__global__ void k_scan1() {
    int tid = threadIdx.x;
    int i = blockIdx.x * 1024 + tid;
    int lane = tid & 31, wid = tid >> 5;
    int v = (i < N_NODES) ? g_indeg[i] : 0;
    if (i < N_NODES) g_dinv[i] = rsqrtf((float)(v + 1));
    int s = v;
    #pragma unroll
    for (int off = 1; off < 32; off <<= 1) {
        int t = __shfl_up_sync(0xffffffffu, s, off);
        if (lane >= off) s += t;
    }
    __shared__ int wsum[32];
    if (lane == 31) wsum[wid] = s;
    __syncthreads();
    if (wid == 0) {
        int w = wsum[lane];
        #pragma unroll
        for (int off = 1; off < 32; off <<= 1) {
            int t = __shfl_up_sync(0xffffffffu, w, off);
            if (lane >= off) w += t;
        }
        wsum[lane] = w;
    }
    __syncthreads();
    int incl = s + (wid ? wsum[wid - 1] : 0);
    if (i < N_NODES) g_rowptr[i + 1] = incl;
    if (tid == 1023) g_bsum[blockIdx.x] = incl;
}

// scan3: each block computes its own carry from g_bsum (no separate scan2)
__global__ void k_scan3() {
    __shared__ int soff;
    int tid = threadIdx.x, lane = tid & 31;
    if (tid < 32) {
        int acc = 0;
        for (int j = lane; j < blockIdx.x; j += 32) acc += g_bsum[j];
        #pragma unroll
        for (int off = 16; off; off >>= 1)
            acc += __shfl_xor_sync(0xffffffffu, acc, off);
        if (lane == 0) soff = acc;
    }
    __syncthreads();
    int i = blockIdx.x * 1024 + tid;
    if (i < N_NODES) g_rowptr[i + 1] += soff;
    if (i == 0) g_rowptr[0] = 0;
}

__global__ void k_fill(const void* __restrict__ ei) {
    int e = blockIdx.x * blockDim.x + threadIdx.x;
    if (e < N_EDGES) {
        int c = load_idx(ei, (size_t)N_EDGES + e);
        int pos = g_rowptr[c] + atomicAdd(&g_cursor[c], 1);
        g_csrsrc[pos] = load_idx(ei, e);
    }
}

// ---------------- HMMA GEMM: g_t = dinv * (A @ W) ----------------
// bf16 hi/lo split, 3-term mma.sync (Ah*Bh + Ah*Bl + Al*Bh), fp32 acc.
// B = W^T staged in smem. A fragments loaded directly from gmem per warp.
#define APAD 136

__device__ __forceinline__ void mma16816(float* d, const uint32_t* a,
                                         uint32_t b0, uint32_t b1) {
    asm volatile(
        "mma.sync.aligned.m16n8k16.row.col.f32.bf16.bf16.f32 "
        "{%0,%1,%2,%3}, {%4,%5,%6,%7}, {%8,%9}, {%0,%1,%2,%3};"
        : "+f"(d[0]), "+f"(d[1]), "+f"(d[2]), "+f"(d[3])
        : "r"(a[0]), "r"(a[1]), "r"(a[2]), "r"(a[3]), "r"(b0), "r"(b1));
}

__device__ __forceinline__ void split2(float2 v, uint32_t& hi, uint32_t& lo) {
    __nv_bfloat16 h0 = __float2bfloat16(v.x), h1 = __float2bfloat16(v.y);
    __nv_bfloat16 l0 = __float2bfloat16(v.x - __bfloat162float(h0));
    __nv_bfloat16 l1 = __float2bfloat16(v.y - __bfloat162float(h1));
    __nv_bfloat162 H(h0, h1), L(l0, l1);
    hi = *(uint32_t*)&H;
    lo = *(uint32_t*)&L;
}

template <int NC, bool FROM_GH>
__global__ __launch_bounds__(256, 2) void k_mma(const float* __restrict__ Ax,
                                                const float* __restrict__ W) {
    const float* __restrict__ A = FROM_GH ? (const float*)g_h : Ax;
    extern __shared__ __nv_bfloat16 sm[];
    __nv_bfloat16* BH = sm;                    // [NC][APAD]
    __nv_bfloat16* BL = BH + NC * APAD;

    const int tid = threadIdx.x;
    const int wid = tid >> 5, lane = tid & 31;
    const int base = blockIdx.x * 128;

    // ---- stage B = W^T: W[k][n] -> B[n][k], hi/lo split ----
    for (int idx = tid; idx < 128 * NC; idx += 256) {
        int k = idx / NC, n = idx % NC;        // coalesced W read
        float w = W[idx];
        __nv_bfloat16 h = __float2bfloat16(w);
        BH[n * APAD + k] = h;
        BL[n * APAD + k] = __float2bfloat16(w - __bfloat162float(h));
    }
    __syncthreads();

    constexpr int NT = NC / 8;
    float acc[NT][4];
    #pragma unroll
    for (int t = 0; t < NT; t++)
        #pragma unroll
        for (int j = 0; j < 4; j++) acc[t][j] = 0.f;

    const int g = lane >> 2;                   // 0..7
    const int kq = (lane & 3) * 2;             // 0,2,4,6
    const int r0 = wid * 16 + g, r1 = r0 + 8;
    const int gr0 = base + r0, gr1 = base + r1;
    const bool v0 = gr0 < N_NODES, v1 = gr1 < N_NODES;
    const float* A0 = A + (size_t)gr0 * 128;
    const float* A1 = A + (size_t)gr1 * 128;

    #pragma unroll
    for (int ks = 0; ks < 8; ks++) {
        int kb = ks * 16 + kq;
        float2 z = make_float2(0.f, 0.f);
        float2 va0 = v0 ? *(const float2*)(A0 + kb)     : z;
        float2 va1 = v1 ? *(const float2*)(A1 + kb)     : z;
        float2 vb0 = v0 ? *(const float2*)(A0 + kb + 8) : z;
        float2 vb1 = v1 ? *(const float2*)(A1 + kb + 8) : z;
        uint32_t ah[4], al[4];
        split2(va0, ah[0], al[0]);
        split2(va1, ah[1], al[1]);
        split2(vb0, ah[2], al[2]);
        split2(vb1, ah[3], al[3]);
        #pragma unroll
        for (int nt = 0; nt < NT; nt++) {
            int n = nt * 8 + g;
            uint32_t bh0 = *(const uint32_t*)(BH + n * APAD + kb);
            uint32_t bh1 = *(const uint32_t*)(BH + n * APAD + kb + 8);
            uint32_t bl0 = *(const uint32_t*)(BL + n * APAD + kb);
            uint32_t bl1 = *(const uint32_t*)(BL + n * APAD + kb + 8);
            mma16816(acc[nt], ah, bh0, bh1);
            mma16816(acc[nt], ah, bl0, bl1);
            mma16816(acc[nt], al, bh0, bh1);
        }
    }

    // ---- epilogue: scale by dinv, write g_t ----
    float d0 = v0 ? g_dinv[gr0] : 0.f;
    float d1 = v1 ? g_dinv[gr1] : 0.f;
    #pragma unroll
    for (int nt = 0; nt < NT; nt++) {
        int col = nt * 8 + kq;
        if (v0)
            *(float2*)(g_t + (size_t)gr0 * NC + col) = make_float2(d0 * acc[nt][0], d0 * acc[nt][1]);
        if (v1)
            *(float2*)(g_t + (size_t)gr1 * NC + col) = make_float2(d1 * acc[nt][2], d1 * acc[nt][3]);
    }
}

// ---------------- aggregation (layers 1,2): g_h = relu(dinv*(u[v]+sum u[src])+b) ----------------
__global__ void k_agg128(const float* __restrict__ bias) {
    int gw = (blockIdx.x * blockDim.x + threadIdx.x) >> 5;
    int lane = threadIdx.x & 31;
    if (gw >= N_NODES) return;
    int beg = g_rowptr[gw], end = g_rowptr[gw + 1];
    float d = g_dinv[gw];

    float4 a = *((const float4*)(g_t + (size_t)gw * 128) + lane);
    int e = beg;
    for (; e + 4 <= end; e += 4) {
        int s0 = g_csrsrc[e], s1 = g_csrsrc[e + 1], s2 = g_csrsrc[e + 2], s3 = g_csrsrc[e + 3];
        float4 u0 = *((const float4*)(g_t + (size_t)s0 * 128) + lane);
        float4 u1 = *((const float4*)(g_t + (size_t)s1 * 128) + lane);
        float4 u2 = *((const float4*)(g_t + (size_t)s2 * 128) + lane);
        float4 u3 = *((const float4*)(g_t + (size_t)s3 * 128) + lane);
        a.x += (u0.x + u1.x) + (u2.x + u3.x);
        a.y += (u0.y + u1.y) + (u2.y + u3.y);
        a.z += (u0.z + u1.z) + (u2.z + u3.z);
        a.w += (u0.w + u1.w) + (u2.w + u3.w);
    }
    for (; e < end; e++) {
        int s = g_csrsrc[e];
        float4 u = *((const float4*)(g_t + (size_t)s * 128) + lane);
        a.x += u.x; a.y += u.y; a.z += u.z; a.w += u.w;
    }
    float4 bb = *((const float4*)bias + lane);
    float4 o;
    o.x = fmaxf(fmaf(d, a.x, bb.x), 0.f);
    o.y = fmaxf(fmaf(d, a.y, bb.y), 0.f);
    o.z = fmaxf(fmaf(d, a.z, bb.z), 0.f);
    o.w = fmaxf(fmaf(d, a.w, bb.w), 0.f);
    *((float4*)(g_h + (size_t)gw * 128) + lane) = o;
}

// ---------------- layer-3 aggregation fused with mean-pool accumulation ----------------
__global__ void k_agg_pool(const float* __restrict__ bias, const void* __restrict__ batch) {
    int gw = (blockIdx.x * blockDim.x + threadIdx.x) >> 5;
    int lane = threadIdx.x & 31;
    if (gw >= N_NODES) return;
    int beg = g_rowptr[gw], end = g_rowptr[gw + 1];
    float d = g_dinv[gw];

    float2 a = *((const float2*)(g_t + (size_t)gw * 64) + lane);
    int e = beg;
    for (; e + 4 <= end; e += 4) {
        int s0 = g_csrsrc[e], s1 = g_csrsrc[e + 1], s2 = g_csrsrc[e + 2], s3 = g_csrsrc[e + 3];
        float2 u0 = *((const float2*)(g_t + (size_t)s0 * 64) + lane);
        float2 u1 = *((const float2*)(g_t + (size_t)s1 * 64) + lane);
        float2 u2 = *((const float2*)(g_t + (size_t)s2 * 64) + lane);
        float2 u3 = *((const float2*)(g_t + (size_t)s3 * 64) + lane);
        a.x += (u0.x + u1.x) + (u2.x + u3.x);
        a.y += (u0.y + u1.y) + (u2.y + u3.y);
    }
    for (; e < end; e++) {
        int s = g_csrsrc[e];
        float2 u = *((const float2*)(g_t + (size_t)s * 64) + lane);
        a.x += u.x; a.y += u.y;
    }
    float2 bb = *((const float2*)bias + lane);
    float ox = fmaxf(fmaf(d, a.x, bb.x), 0.f);
    float oy = fmaxf(fmaf(d, a.y, bb.y), 0.f);

    int g = load_idx(batch, gw);
    atomicAdd(&g_pool[g * 64 + lane * 2], ox);
    atomicAdd(&g_pool[g * 64 + lane * 2 + 1], oy);
    if (lane == 0) atomicAdd(&g_cnt[g], 1.f);
}

// ---------------- FC head (single block) ----------------
__global__ void k_fc(const float* __restrict__ Wf1, const float* __restrict__ bf1,
                     const float* __restrict__ Wf2, const float* __restrict__ bf2,
                     float* __restrict__ out) {
    __shared__ float p[64 * 64];
    __shared__ float a1[64 * 32];
    int tid = threadIdx.x;
    for (int i = tid; i < 64 * 64; i += 256) {
        int g = i >> 6;
        p[i] = g_pool[i] / fmaxf(g_cnt[g], 1.f);
    }
    __syncthreads();
    for (int i = tid; i < 64 * 32; i += 256) {
        int g = i >> 5, c = i & 31;
        float s = bf1[c];
        #pragma unroll 8
        for (int k = 0; k < 64; k++) s = fmaf(p[g * 64 + k], Wf1[k * 32 + c], s);
        a1[i] = fmaxf(s, 0.f);
    }
    __syncthreads();
    for (int i = tid; i < 64 * 10; i += 256) {
        int g = i / 10, c = i % 10;
        float s = bf2[c];
        #pragma unroll
        for (int k = 0; k < 32; k++) s = fmaf(a1[g * 32 + k], Wf2[k * 10 + c], s);
        out[i] = s;
    }
}

// ---------------- launch ----------------
extern "C" void kernel_launch(void* const* d_in, const int* in_sizes, int n_in,
                              void* d_out, int out_size) {
    const float* x     = (const float*)d_in[0];
    const void*  ei    = d_in[1];
    const void*  batch = d_in[2];
    const float* W1  = (const float*)d_in[3];
    const float* b1  = (const float*)d_in[4];
    const float* W2  = (const float*)d_in[5];
    const float* b2  = (const float*)d_in[6];
    const float* W3  = (const float*)d_in[7];
    const float* b3  = (const float*)d_in[8];
    const float* Wf1 = (const float*)d_in[9];
    const float* bf1 = (const float*)d_in[10];
    const float* Wf2 = (const float*)d_in[11];
    const float* bf2 = (const float*)d_in[12];
    float* out = (float*)d_out;

    const int EB = (N_EDGES + 255) / 256;
    const int AB = (N_NODES * 32 + 255) / 256;
    const int MB = (N_NODES + 127) / 128;      // 391

    const int SM128 = 2 * 128 * APAD * 2;      // 69632 (B hi+lo)
    const int SM64  = 2 * 64 * APAD * 2;       // 34816
    cudaFuncSetAttribute(k_mma<128, false>, cudaFuncAttributeMaxDynamicSharedMemorySize, SM128);
    cudaFuncSetAttribute(k_mma<128, true>,  cudaFuncAttributeMaxDynamicSharedMemorySize, SM128);
    cudaFuncSetAttribute(k_mma<64, true>,   cudaFuncAttributeMaxDynamicSharedMemorySize, SM64);

    k_zero<<<64, 256>>>((const int*)ei);
    k_hist<<<EB, 256>>>(ei);
    k_scan1<<<SCAN_BLOCKS, 1024>>>();
    k_scan3<<<SCAN_BLOCKS, 1024>>>();
    k_fill<<<EB, 256>>>(ei);

    k_mma<128, false><<<MB, 256, SM128>>>(x, W1);
    k_agg128<<<AB, 256>>>(b1);
    k_mma<128, true><<<MB, 256, SM128>>>(nullptr, W2);
    k_agg128<<<AB, 256>>>(b2);
    k_mma<64, true><<<MB, 256, SM64>>>(nullptr, W3);
    k_agg_pool<<<AB, 256>>>(b3, batch);

    k_fc<<<1, 256>>>(Wf1, bf1, Wf2, bf2, out);
}

// round 16
// speedup vs baseline: 1.5022x; 1.1092x over previous
#include <cuda_runtime.h>
#include <cuda_bf16.h>
#include <cuda_fp16.h>
#include <cstdint>

#define N_NODES 50000
#define N_EDGES 600000
#define N_GRAPHS 64
#define SCAN_BLOCKS ((N_NODES + 1023) / 1024)   // 49

// ---------------- scratch (no allocations allowed) ----------------
__device__ __half g_t[(size_t)N_NODES * 128];  // GEMM output u = dinv*(h@W), fp16
__device__ float  g_h[(size_t)N_NODES * 128];  // layer activations (fp32)
__device__ float  g_dinv[N_NODES];
__device__ int    g_indeg[N_NODES];
__device__ int    g_rowptr[N_NODES + 1];
__device__ int    g_cursor[N_NODES];
__device__ int    g_csrsrc[N_EDGES];
__device__ int    g_bsum[SCAN_BLOCKS];
__device__ float  g_pool[N_GRAPHS * 64];
__device__ float  g_cnt[N_GRAPHS];
__device__ int    g_is64;

// index loader robust to int32 vs int64 storage
__device__ __forceinline__ int load_idx(const void* __restrict__ p, size_t i) {
    if (g_is64) return (int)((const long long*)p)[i];
    return ((const int*)p)[i];
}

// load 4 consecutive fp16 t-elements for this lane -> float4 (one LDG.64)
__device__ __forceinline__ float4 ldt4(const __half* __restrict__ p, int lane) {
    uint2 raw = *((const uint2*)p + lane);
    __half2 a = *(__half2*)&raw.x, b = *(__half2*)&raw.y;
    float2 fa = __half22float2(a), fb = __half22float2(b);
    return make_float4(fa.x, fa.y, fb.x, fb.y);
}

// ---------------- zero + dtype detect (fused) ----------------
__global__ void k_zero(const int* __restrict__ ei_words) {
    int i = blockIdx.x * blockDim.x + threadIdx.x;
    int stride = gridDim.x * blockDim.x;
    if (blockIdx.x == 0 && threadIdx.x < 32) {
        int lane = threadIdx.x;
        int nz = 0;
        for (int j = lane; j < 256; j += 32)
            nz |= ei_words[2 * j + 1];          // candidate int64 high words
        for (int off = 16; off; off >>= 1)
            nz |= __shfl_xor_sync(0xffffffffu, nz, off);
        if (lane == 0) g_is64 = (nz == 0) ? 1 : 0;
    }
    for (int j = i; j < N_NODES; j += stride) { g_indeg[j] = 0; g_cursor[j] = 0; }
    if (i < N_GRAPHS * 64) g_pool[i] = 0.f;
    if (i < N_GRAPHS) g_cnt[i] = 0.f;
}

__global__ void k_hist(const void* __restrict__ ei) {
    int e = blockIdx.x * blockDim.x + threadIdx.x;
    if (e < N_EDGES) atomicAdd(&g_indeg[load_idx(ei, (size_t)N_EDGES + e)], 1);
}

__global__ void k_scan1() {
    int tid = threadIdx.x;
    int i = blockIdx.x * 1024 + tid;
    int lane = tid & 31, wid = tid >> 5;
    int v = (i < N_NODES) ? g_indeg[i] : 0;
    if (i < N_NODES) g_dinv[i] = rsqrtf((float)(v + 1));
    int s = v;
    #pragma unroll
    for (int off = 1; off < 32; off <<= 1) {
        int t = __shfl_up_sync(0xffffffffu, s, off);
        if (lane >= off) s += t;
    }
    __shared__ int wsum[32];
    if (lane == 31) wsum[wid] = s;
    __syncthreads();
    if (wid == 0) {
        int w = wsum[lane];
        #pragma unroll
        for (int off = 1; off < 32; off <<= 1) {
            int t = __shfl_up_sync(0xffffffffu, w, off);
            if (lane >= off) w += t;
        }
        wsum[lane] = w;
    }
    __syncthreads();
    int incl = s + (wid ? wsum[wid - 1] : 0);
    if (i < N_NODES) g_rowptr[i + 1] = incl;
    if (tid == 1023) g_bsum[blockIdx.x] = incl;
}

// scan3: each block computes its own carry from g_bsum (no separate scan2)
__global__ void k_scan3() {
    __shared__ int soff;
    int tid = threadIdx.x, lane = tid & 31;
    if (tid < 32) {
        int acc = 0;
        for (int j = lane; j < blockIdx.x; j += 32) acc += g_bsum[j];
        #pragma unroll
        for (int off = 16; off; off >>= 1)
            acc += __shfl_xor_sync(0xffffffffu, acc, off);
        if (lane == 0) soff = acc;
    }
    __syncthreads();
    int i = blockIdx.x * 1024 + tid;
    if (i < N_NODES) g_rowptr[i + 1] += soff;
    if (i == 0) g_rowptr[0] = 0;
}

__global__ void k_fill(const void* __restrict__ ei) {
    int e = blockIdx.x * blockDim.x + threadIdx.x;
    if (e < N_EDGES) {
        int c = load_idx(ei, (size_t)N_EDGES + e);
        int pos = g_rowptr[c] + atomicAdd(&g_cursor[c], 1);
        g_csrsrc[pos] = load_idx(ei, e);
    }
}

// ---------------- HMMA GEMM: g_t = fp16( dinv * (A @ W) ) ----------------
// bf16 hi/lo split, 3-term mma.sync (Ah*Bh + Ah*Bl + Al*Bh), fp32 acc.
// B = W^T staged in smem. A fragments loaded directly from gmem per warp.
#define APAD 136

__device__ __forceinline__ void mma16816(float* d, const uint32_t* a,
                                         uint32_t b0, uint32_t b1) {
    asm volatile(
        "mma.sync.aligned.m16n8k16.row.col.f32.bf16.bf16.f32 "
        "{%0,%1,%2,%3}, {%4,%5,%6,%7}, {%8,%9}, {%0,%1,%2,%3};"
        : "+f"(d[0]), "+f"(d[1]), "+f"(d[2]), "+f"(d[3])
        : "r"(a[0]), "r"(a[1]), "r"(a[2]), "r"(a[3]), "r"(b0), "r"(b1));
}

__device__ __forceinline__ void split2(float2 v, uint32_t& hi, uint32_t& lo) {
    __nv_bfloat16 h0 = __float2bfloat16(v.x), h1 = __float2bfloat16(v.y);
    __nv_bfloat16 l0 = __float2bfloat16(v.x - __bfloat162float(h0));
    __nv_bfloat16 l1 = __float2bfloat16(v.y - __bfloat162float(h1));
    __nv_bfloat162 H(h0, h1), L(l0, l1);
    hi = *(uint32_t*)&H;
    lo = *(uint32_t*)&L;
}

template <int NC, bool FROM_GH>
__global__ __launch_bounds__(256, 2) void k_mma(const float* __restrict__ Ax,
                                                const float* __restrict__ W) {
    const float* __restrict__ A = FROM_GH ? (const float*)g_h : Ax;
    extern __shared__ __nv_bfloat16 sm[];
    __nv_bfloat16* BH = sm;                    // [NC][APAD]
    __nv_bfloat16* BL = BH + NC * APAD;

    const int tid = threadIdx.x;
    const int wid = tid >> 5, lane = tid & 31;
    const int base = blockIdx.x * 128;

    // ---- stage B = W^T: W[k][n] -> B[n][k], hi/lo split ----
    for (int idx = tid; idx < 128 * NC; idx += 256) {
        int k = idx / NC, n = idx % NC;        // coalesced W read
        float w = W[idx];
        __nv_bfloat16 h = __float2bfloat16(w);
        BH[n * APAD + k] = h;
        BL[n * APAD + k] = __float2bfloat16(w - __bfloat162float(h));
    }
    __syncthreads();

    constexpr int NT = NC / 8;
    float acc[NT][4];
    #pragma unroll
    for (int t = 0; t < NT; t++)
        #pragma unroll
        for (int j = 0; j < 4; j++) acc[t][j] = 0.f;

    const int g = lane >> 2;                   // 0..7
    const int kq = (lane & 3) * 2;             // 0,2,4,6
    const int r0 = wid * 16 + g, r1 = r0 + 8;
    const int gr0 = base + r0, gr1 = base + r1;
    const bool v0 = gr0 < N_NODES, v1 = gr1 < N_NODES;
    const float* A0 = A + (size_t)gr0 * 128;
    const float* A1 = A + (size_t)gr1 * 128;

    #pragma unroll
    for (int ks = 0; ks < 8; ks++) {
        int kb = ks * 16 + kq;
        float2 z = make_float2(0.f, 0.f);
        float2 va0 = v0 ? *(const float2*)(A0 + kb)     : z;
        float2 va1 = v1 ? *(const float2*)(A1 + kb)     : z;
        float2 vb0 = v0 ? *(const float2*)(A0 + kb + 8) : z;
        float2 vb1 = v1 ? *(const float2*)(A1 + kb + 8) : z;
        uint32_t ah[4], al[4];
        split2(va0, ah[0], al[0]);
        split2(va1, ah[1], al[1]);
        split2(vb0, ah[2], al[2]);
        split2(vb1, ah[3], al[3]);
        #pragma unroll
        for (int nt = 0; nt < NT; nt++) {
            int n = nt * 8 + g;
            uint32_t bh0 = *(const uint32_t*)(BH + n * APAD + kb);
            uint32_t bh1 = *(const uint32_t*)(BH + n * APAD + kb + 8);
            uint32_t bl0 = *(const uint32_t*)(BL + n * APAD + kb);
            uint32_t bl1 = *(const uint32_t*)(BL + n * APAD + kb + 8);
            mma16816(acc[nt], ah, bh0, bh1);
            mma16816(acc[nt], ah, bl0, bl1);
            mma16816(acc[nt], al, bh0, bh1);
        }
    }

    // ---- epilogue: scale by dinv, write fp16 g_t ----
    float d0 = v0 ? g_dinv[gr0] : 0.f;
    float d1 = v1 ? g_dinv[gr1] : 0.f;
    #pragma unroll
    for (int nt = 0; nt < NT; nt++) {
        int col = nt * 8 + kq;
        if (v0)
            *(__half2*)(g_t + (size_t)gr0 * NC + col) =
                __floats2half2_rn(d0 * acc[nt][0], d0 * acc[nt][1]);
        if (v1)
            *(__half2*)(g_t + (size_t)gr1 * NC + col) =
                __floats2half2_rn(d1 * acc[nt][2], d1 * acc[nt][3]);
    }
}

// ---------------- aggregation (layers 1,2): g_h = relu(dinv*(u[v]+sum u[src])+b) ----------------
__global__ void k_agg128(const float* __restrict__ bias) {
    int gw = (blockIdx.x * blockDim.x + threadIdx.x) >> 5;
    int lane = threadIdx.x & 31;
    if (gw >= N_NODES) return;
    int beg = g_rowptr[gw], end = g_rowptr[gw + 1];
    float d = g_dinv[gw];

    float4 a = ldt4(g_t + (size_t)gw * 128, lane);   // self term
    int e = beg;
    for (; e + 4 <= end; e += 4) {
        int s0 = g_csrsrc[e], s1 = g_csrsrc[e + 1], s2 = g_csrsrc[e + 2], s3 = g_csrsrc[e + 3];
        float4 u0 = ldt4(g_t + (size_t)s0 * 128, lane);
        float4 u1 = ldt4(g_t + (size_t)s1 * 128, lane);
        float4 u2 = ldt4(g_t + (size_t)s2 * 128, lane);
        float4 u3 = ldt4(g_t + (size_t)s3 * 128, lane);
        a.x += (u0.x + u1.x) + (u2.x + u3.x);
        a.y += (u0.y + u1.y) + (u2.y + u3.y);
        a.z += (u0.z + u1.z) + (u2.z + u3.z);
        a.w += (u0.w + u1.w) + (u2.w + u3.w);
    }
    for (; e < end; e++) {
        int s = g_csrsrc[e];
        float4 u = ldt4(g_t + (size_t)s * 128, lane);
        a.x += u.x; a.y += u.y; a.z += u.z; a.w += u.w;
    }
    float4 bb = *((const float4*)bias + lane);
    float4 o;
    o.x = fmaxf(fmaf(d, a.x, bb.x), 0.f);
    o.y = fmaxf(fmaf(d, a.y, bb.y), 0.f);
    o.z = fmaxf(fmaf(d, a.z, bb.z), 0.f);
    o.w = fmaxf(fmaf(d, a.w, bb.w), 0.f);
    *((float4*)(g_h + (size_t)gw * 128) + lane) = o;
}

// ---------------- layer-3 aggregation fused with mean-pool accumulation ----------------
__global__ void k_agg_pool(const float* __restrict__ bias, const void* __restrict__ batch) {
    int gw = (blockIdx.x * blockDim.x + threadIdx.x) >> 5;
    int lane = threadIdx.x & 31;
    if (gw >= N_NODES) return;
    int beg = g_rowptr[gw], end = g_rowptr[gw + 1];
    float d = g_dinv[gw];

    float2 a = __half22float2(*((const __half2*)(g_t + (size_t)gw * 64) + lane));
    int e = beg;
    for (; e + 4 <= end; e += 4) {
        int s0 = g_csrsrc[e], s1 = g_csrsrc[e + 1], s2 = g_csrsrc[e + 2], s3 = g_csrsrc[e + 3];
        float2 u0 = __half22float2(*((const __half2*)(g_t + (size_t)s0 * 64) + lane));
        float2 u1 = __half22float2(*((const __half2*)(g_t + (size_t)s1 * 64) + lane));
        float2 u2 = __half22float2(*((const __half2*)(g_t + (size_t)s2 * 64) + lane));
        float2 u3 = __half22float2(*((const __half2*)(g_t + (size_t)s3 * 64) + lane));
        a.x += (u0.x + u1.x) + (u2.x + u3.x);
        a.y += (u0.y + u1.y) + (u2.y + u3.y);
    }
    for (; e < end; e++) {
        int s = g_csrsrc[e];
        float2 u = __half22float2(*((const __half2*)(g_t + (size_t)s * 64) + lane));
        a.x += u.x; a.y += u.y;
    }
    float2 bb = *((const float2*)bias + lane);
    float ox = fmaxf(fmaf(d, a.x, bb.x), 0.f);
    float oy = fmaxf(fmaf(d, a.y, bb.y), 0.f);

    int g = load_idx(batch, gw);
    atomicAdd(&g_pool[g * 64 + lane * 2], ox);
    atomicAdd(&g_pool[g * 64 + lane * 2 + 1], oy);
    if (lane == 0) atomicAdd(&g_cnt[g], 1.f);
}

// ---------------- FC head (single block) ----------------
__global__ void k_fc(const float* __restrict__ Wf1, const float* __restrict__ bf1,
                     const float* __restrict__ Wf2, const float* __restrict__ bf2,
                     float* __restrict__ out) {
    __shared__ float p[64 * 64];
    __shared__ float a1[64 * 32];
    int tid = threadIdx.x;
    for (int i = tid; i < 64 * 64; i += 256) {
        int g = i >> 6;
        p[i] = g_pool[i] / fmaxf(g_cnt[g], 1.f);
    }
    __syncthreads();
    for (int i = tid; i < 64 * 32; i += 256) {
        int g = i >> 5, c = i & 31;
        float s = bf1[c];
        #pragma unroll 8
        for (int k = 0; k < 64; k++) s = fmaf(p[g * 64 + k], Wf1[k * 32 + c], s);
        a1[i] = fmaxf(s, 0.f);
    }
    __syncthreads();
    for (int i = tid; i < 64 * 10; i += 256) {
        int g = i / 10, c = i % 10;
        float s = bf2[c];
        #pragma unroll
        for (int k = 0; k < 32; k++) s = fmaf(a1[g * 32 + k], Wf2[k * 10 + c], s);
        out[i] = s;
    }
}

// ---------------- launch ----------------
extern "C" void kernel_launch(void* const* d_in, const int* in_sizes, int n_in,
                              void* d_out, int out_size) {
    const float* x     = (const float*)d_in[0];
    const void*  ei    = d_in[1];
    const void*  batch = d_in[2];
    const float* W1  = (const float*)d_in[3];
    const float* b1  = (const float*)d_in[4];
    const float* W2  = (const float*)d_in[5];
    const float* b2  = (const float*)d_in[6];
    const float* W3  = (const float*)d_in[7];
    const float* b3  = (const float*)d_in[8];
    const float* Wf1 = (const float*)d_in[9];
    const float* bf1 = (const float*)d_in[10];
    const float* Wf2 = (const float*)d_in[11];
    const float* bf2 = (const float*)d_in[12];
    float* out = (float*)d_out;

    const int EB = (N_EDGES + 255) / 256;
    const int AB = (N_NODES * 32 + 255) / 256;
    const int MB = (N_NODES + 127) / 128;      // 391

    const int SM128 = 2 * 128 * APAD * 2;      // 69632 (B hi+lo)
    const int SM64  = 2 * 64 * APAD * 2;       // 34816
    cudaFuncSetAttribute(k_mma<128, false>, cudaFuncAttributeMaxDynamicSharedMemorySize, SM128);
    cudaFuncSetAttribute(k_mma<128, true>,  cudaFuncAttributeMaxDynamicSharedMemorySize, SM128);
    cudaFuncSetAttribute(k_mma<64, true>,   cudaFuncAttributeMaxDynamicSharedMemorySize, SM64);

    k_zero<<<64, 256>>>((const int*)ei);
    k_hist<<<EB, 256>>>(ei);
    k_scan1<<<SCAN_BLOCKS, 1024>>>();
    k_scan3<<<SCAN_BLOCKS, 1024>>>();
    k_fill<<<EB, 256>>>(ei);

    k_mma<128, false><<<MB, 256, SM128>>>(x, W1);
    k_agg128<<<AB, 256>>>(b1);
    k_mma<128, true><<<MB, 256, SM128>>>(nullptr, W2);
    k_agg128<<<AB, 256>>>(b2);
    k_mma<64, true><<<MB, 256, SM64>>>(nullptr, W3);
    k_agg_pool<<<AB, 256>>>(b3, batch);

    k_fc<<<1, 256>>>(Wf1, bf1, Wf2, bf2, out);
}